// round 3
// baseline (speedup 1.0000x reference)
#include <cuda_runtime.h>
#include <cuda_bf16.h>

// Problem constants
#define Hc 200          // H
#define Wc 196          // W
#define NPIX (Hc * Wc)  // 39200 pixels per camera
#define NCH 256         // channels
#define NCAM 6
#define SSZ 400         // scene grid side
#define NCELL (SSZ * SSZ)  // 160000

// Scratch (allocation-free rule: __device__ globals)
__device__ float g_sum[NCELL];
__device__ float g_cnt[NCELL];
__device__ int   g_mask_flags;   // bit0: u8 evidence, bit1: f32 evidence

// Zero the grids; block 0 additionally fingerprints the mask buffer dtype.
__global__ void zero_detect_kernel(const unsigned int* __restrict__ mask_words) {
    int i = blockIdx.x * 256 + threadIdx.x;
    if (i < NCELL) {
        g_sum[i] = 0.0f;
        g_cnt[i] = 0.0f;
    }
    if (blockIdx.x == 0) {
        if (threadIdx.x == 0) g_mask_flags = 0;
        __syncthreads();
        int local = 0;
        // If u8: NPIX bytes = 9800 words. If i32/f32: NPIX words. Scanning the
        // first 9800 words is valid & sufficient for all three layouts.
        for (int w = threadIdx.x; w < NPIX / 4; w += 256) {
            unsigned int v = mask_words[w];
            if (v == 0x3F800000u) local |= 2;                       // float 1.0f
            else if ((v & ~0x01010101u) == 0u && (v & 0xFFFFFF00u)) // packed bools
                local |= 1;
        }
        if (local) atomicOr(&g_mask_flags, local);
    }
}

// One thread per (cam, pixel). pix = w*H + h is the memory-contiguous index of
// the (W,H) plane; loop over 256 channels with stride NPIX -> fully coalesced
// streaming of the 241MB feature tensor. Reduce to scalar dot with w_cls,
// then scatter the scalar + count into the 400x400 BEV grid.
__global__ __launch_bounds__(256) void bev_dot_scatter_kernel(
    const float* __restrict__ feats,   // [NCAM, NCH, Wc, Hc]
    const float* __restrict__ mats,    // [NCAM, 4, 4]
    const float* __restrict__ lc,      // [4, NPIX]  (gx, gy, 0, 1), n = h*W + w
    const void*  __restrict__ mask_raw,// [NPIX] bool in unknown storage dtype
    const float* __restrict__ w_cls)   // [NCH]
{
    __shared__ float sw[NCH];
    __shared__ float sm[8];  // rows 0,1 of this cam's 4x4

    const int tid = threadIdx.x;
    const int cam = blockIdx.y;

    sw[tid] = w_cls[tid];
    if (tid < 8) sm[tid] = mats[cam * 16 + tid];
    __syncthreads();

    const int pix = blockIdx.x * 256 + tid;
    if (pix >= NPIX) return;

    const float* p = feats + (size_t)cam * NCH * NPIX + pix;

    float a0 = 0.f, a1 = 0.f, a2 = 0.f, a3 = 0.f;
#pragma unroll 8
    for (int ch = 0; ch < NCH; ch += 4) {
        a0 = fmaf(p[(ch + 0) * NPIX], sw[ch + 0], a0);
        a1 = fmaf(p[(ch + 1) * NPIX], sw[ch + 1], a1);
        a2 = fmaf(p[(ch + 2) * NPIX], sw[ch + 2], a2);
        a3 = fmaf(p[(ch + 3) * NPIX], sw[ch + 3], a3);
    }
    const float dot = (a0 + a1) + (a2 + a3);

    // pix = w*H + h ; logical flat index n = h*W + w
    const int wq = pix / Hc;
    const int h  = pix - wq * Hc;
    const int n  = h * Wc + wq;

    // dtype-robust mask read
    const int flags = g_mask_flags;
    bool m;
    if (flags & 2)      m = ((const float*)mask_raw)[n] != 0.0f;
    else if (flags & 1) m = ((const unsigned char*)mask_raw)[n] != 0;
    else                m = ((const int*)mask_raw)[n] != 0;

    if (m) {
        const float gx = lc[n];
        const float gy = lc[NPIX + n];
        const float x = sm[0] * gx + sm[1] * gy + sm[3];
        const float y = sm[4] * gx + sm[5] * gy + sm[7];
        // (coord + 100) / 0.5 == (coord + 100) * 2 exactly; jnp.round == rintf
        const float fx = rintf((x + 100.0f) * 2.0f);
        const float fy = rintf((y + 100.0f) * 2.0f);
        if (fx >= 0.0f && fx < (float)SSZ && fy >= 0.0f && fy < (float)SSZ) {
            const int cell = (int)fx * SSZ + (int)fy;
            atomicAdd(&g_sum[cell], dot);
            atomicAdd(&g_cnt[cell], 1.0f);
        }
    }
}

__global__ void finalize_kernel(float* __restrict__ out,
                                const float* __restrict__ b_cls) {
    int i = blockIdx.x * 256 + threadIdx.x;
    if (i < NCELL) {
        const float c = g_cnt[i];
        // where(cnt>=1, sum/max(cnt,1), sum) == sum/max(cnt,1): sum==0 when cnt==0
        out[i] = g_sum[i] / fmaxf(c, 1.0f) + b_cls[0];
    }
}

extern "C" void kernel_launch(void* const* d_in, const int* in_sizes, int n_in,
                              void* d_out, int out_size) {
    // Resolve inputs by element count (all distinct) — robust to metadata order.
    const float* feats = 0; const float* mats = 0; const float* lc = 0;
    const void*  mask  = 0; const float* w_cls = 0; const float* b_cls = 0;
    for (int i = 0; i < n_in; i++) {
        switch (in_sizes[i]) {
            case 60211200: feats = (const float*)d_in[i]; break;  // td_feats
            case 96:       mats  = (const float*)d_in[i]; break;  // cam_to_ego
            case 156800:   lc    = (const float*)d_in[i]; break;  // logits_coordinates
            case 39200:    mask  = d_in[i];               break;  // single_mask
            case 256:      w_cls = (const float*)d_in[i]; break;  // w_cls
            case 1:        b_cls = (const float*)d_in[i]; break;  // b_cls
        }
    }
    float* out = (float*)d_out;

    zero_detect_kernel<<<(NCELL + 255) / 256, 256>>>((const unsigned int*)mask);

    dim3 grid((NPIX + 255) / 256, NCAM);
    bev_dot_scatter_kernel<<<grid, 256>>>(feats, mats, lc, mask, w_cls);

    finalize_kernel<<<(NCELL + 255) / 256, 256>>>(out, b_cls);
}